// round 5
// baseline (speedup 1.0000x reference)
#include <cuda_runtime.h>

// CBOW negative-sampling loss, fused single-launch. 2 examples per warp.
// Shapes (fixed): B=16384, C=10, K=8, D=128, VOCAB=100000.
// d_in: contexts[B,C] i32, focus_word[B,K] i32, weight_mask[B,K] f32,
//       labels[B,K] f32, ctx_emb[V,D] f32, neg_emb[V,D] f32.
// d_out: 1 float (batch-mean loss).

#define B_N 16384
#define C_N 10
#define K_N 8
#define D_N 128
#define WARPS_PER_BLOCK 8
#define EX_PER_WARP 2
#define THREADS (WARPS_PER_BLOCK * 32)              // 256
#define EX_PER_BLOCK (WARPS_PER_BLOCK * EX_PER_WARP) // 16
#define NBLOCKS (B_N / EX_PER_BLOCK)                // 1024

__device__ float        g_partials[NBLOCKS];
__device__ unsigned int g_count;                    // zero-init; self-resetting

__global__ __launch_bounds__(THREADS, 5)            // cap regs ~51, >=40 warps/SM
void cbow_loss_kernel(const int*   __restrict__ contexts,
                      const int*   __restrict__ focus,
                      const float* __restrict__ wmask,
                      const float* __restrict__ labels,
                      const float* __restrict__ ctx_emb,
                      const float* __restrict__ neg_emb,
                      float*       __restrict__ out)
{
    const int warp = threadIdx.x >> 5;
    const int lane = threadIdx.x & 31;
    const int b0   = (blockIdx.x * WARPS_PER_BLOCK + warp) * EX_PER_WARP;
    const int b1   = b0 + 1;
    const unsigned FULL = 0xffffffffu;

    // ---- lane-distributed index loads: 36 indices in 2 LDGs ----
    // idxA: lanes 0-9 ctx[b0], 10-19 ctx[b1], 20-27 focus[b0], 28-31 focus[b1][0..3]
    // idxB: all lanes load focus[b1][4 + (lane&3)]
    const int* pA;
    if      (lane < 10) pA = contexts + b0 * C_N + lane;
    else if (lane < 20) pA = contexts + b1 * C_N + (lane - 10);
    else if (lane < 28) pA = focus    + b0 * K_N + (lane - 20);
    else                pA = focus    + b1 * K_N + (lane - 28);
    const int idxA = __ldg(pA);
    const int idxB = __ldg(focus + b1 * K_N + 4 + (lane & 3));

    // ---- sum-pool 10 context rows per example; lane owns 4 columns ----
    // 20 independent LDG.128 (L1-bypass) per warp.
    float4 s0 = make_float4(0.f, 0.f, 0.f, 0.f);
    float4 s1 = make_float4(0.f, 0.f, 0.f, 0.f);
#pragma unroll
    for (int c = 0; c < C_N; c++) {
        const int i0 = __shfl_sync(FULL, idxA, c);
        const int i1 = __shfl_sync(FULL, idxA, 10 + c);
        const float4 v0 = __ldcg(reinterpret_cast<const float4*>(ctx_emb + (size_t)i0 * D_N) + lane);
        const float4 v1 = __ldcg(reinterpret_cast<const float4*>(ctx_emb + (size_t)i1 * D_N) + lane);
        s0.x += v0.x; s0.y += v0.y; s0.z += v0.z; s0.w += v0.w;
        s1.x += v1.x; s1.y += v1.y; s1.z += v1.z; s1.w += v1.w;
    }

    // ---- 16 per-lane partial dots (independent LDG.128, L1-bypass) ----
    float p0[K_N], p1[K_N];
#pragma unroll
    for (int k = 0; k < K_N; k++) {
        const int j0 = __shfl_sync(FULL, idxA, 20 + k);
        const int j1 = (k < 4) ? __shfl_sync(FULL, idxA, 28 + k)
                               : __shfl_sync(FULL, idxB, k - 4);
        const float4 t0 = __ldcg(reinterpret_cast<const float4*>(neg_emb + (size_t)j0 * D_N) + lane);
        const float4 t1 = __ldcg(reinterpret_cast<const float4*>(neg_emb + (size_t)j1 * D_N) + lane);
        p0[k] = s0.x * t0.x + s0.y * t0.y + s0.z * t0.z + s0.w * t0.w;
        p1[k] = s1.x * t1.x + s1.y * t1.y + s1.z * t1.z + s1.w * t1.w;
    }

    // ---- packed multi-reduce: 8 dot-reductions per example ----
    // Lane bits 4,3,2 pick pred index; after rounds each lane holds full dot
    // for k(lane) = bit4 | bit3<<1 | bit2<<2.
    float c40[4], c41[4];
#pragma unroll
    for (int j = 0; j < 4; j++) {
        const bool lo = (lane & 16) == 0;
        float k0 = lo ? p0[2 * j] : p0[2 * j + 1];
        float g0 = lo ? p0[2 * j + 1] : p0[2 * j];
        c40[j] = k0 + __shfl_xor_sync(FULL, g0, 16);
        float k1 = lo ? p1[2 * j] : p1[2 * j + 1];
        float g1 = lo ? p1[2 * j + 1] : p1[2 * j];
        c41[j] = k1 + __shfl_xor_sync(FULL, g1, 16);
    }
    float e20[2], e21[2];
#pragma unroll
    for (int j = 0; j < 2; j++) {
        const bool lo = (lane & 8) == 0;
        float k0 = lo ? c40[2 * j] : c40[2 * j + 1];
        float g0 = lo ? c40[2 * j + 1] : c40[2 * j];
        e20[j] = k0 + __shfl_xor_sync(FULL, g0, 8);
        float k1 = lo ? c41[2 * j] : c41[2 * j + 1];
        float g1 = lo ? c41[2 * j + 1] : c41[2 * j];
        e21[j] = k1 + __shfl_xor_sync(FULL, g1, 8);
    }
    float f0v, f1v;
    {
        const bool lo = (lane & 4) == 0;
        float k0 = lo ? e20[0] : e20[1];
        float g0 = lo ? e20[1] : e20[0];
        f0v = k0 + __shfl_xor_sync(FULL, g0, 4);
        float k1 = lo ? e21[0] : e21[1];
        float g1 = lo ? e21[1] : e21[0];
        f1v = k1 + __shfl_xor_sync(FULL, g1, 4);
    }
    f0v += __shfl_xor_sync(FULL, f0v, 2);
    f0v += __shfl_xor_sync(FULL, f0v, 1);
    f1v += __shfl_xor_sync(FULL, f1v, 2);
    f1v += __shfl_xor_sync(FULL, f1v, 1);
    const int k = ((lane >> 4) & 1) | (((lane >> 3) & 1) << 1) | (((lane >> 2) & 1) << 2);

    // ---- per-lane weighted BCE terms (each k on 4 lanes; dup cancels) ----
    const float w0 = __ldg(&wmask[b0 * K_N + k]);
    const float y0 = __ldg(&labels[b0 * K_N + k]);
    const float w1 = __ldg(&wmask[b1 * K_N + k]);
    const float y1 = __ldg(&labels[b1 * K_N + k]);
    const float bce0 = w0 * (fmaxf(f0v, 0.f) + log1pf(__expf(-fabsf(f0v))) - f0v * y0);
    const float bce1 = w1 * (fmaxf(f1v, 0.f) + log1pf(__expf(-fabsf(f1v))) - f1v * y1);

    // ---- packed pair-reduce per example: sum(bce) lower half, sum(w) upper ----
    float r0, r1;
    {
        const bool lo = lane < 16;
        float ka = lo ? bce0 : w0;
        float ga = lo ? w0 : bce0;
        r0 = ka + __shfl_xor_sync(FULL, ga, 16);
        float kb = lo ? bce1 : w1;
        float gb = lo ? w1 : bce1;
        r1 = kb + __shfl_xor_sync(FULL, gb, 16);
    }
#pragma unroll
    for (int off = 8; off; off >>= 1) {
        r0 += __shfl_xor_sync(FULL, r0, off);
        r1 += __shfl_xor_sync(FULL, r1, off);
    }
    const float wt0 = __shfl_sync(FULL, r0, 16);
    const float wt1 = __shfl_sync(FULL, r1, 16);
    const float pair = r0 / wt0 + r1 / wt1;         // per_row(b0) + per_row(b1)

    // ---- deterministic block partial ----
    __shared__ float ws[WARPS_PER_BLOCK];
    __shared__ bool  is_last;
    if (lane == 0) ws[warp] = pair;
    __syncthreads();
    if (threadIdx.x == 0) {
        float s = 0.f;
#pragma unroll
        for (int i = 0; i < WARPS_PER_BLOCK; i++) s += ws[i];
        g_partials[blockIdx.x] = s;
        unsigned prev;
        asm volatile("atom.acq_rel.gpu.global.add.u32 %0, [%1], %2;"
                     : "=r"(prev)
                     : "l"(&g_count), "r"(1u)
                     : "memory");
        is_last = (prev == (unsigned)(NBLOCKS - 1));
    }
    __syncthreads();

    // ---- last block: deterministic final reduction + counter reset ----
    if (is_last) {
        const int tid = threadIdx.x;                // 256 threads, 1024 partials
        float v = 0.f;
#pragma unroll
        for (int j = 0; j < NBLOCKS / THREADS; j++)
            v += __ldcg(&g_partials[tid + j * THREADS]);
#pragma unroll
        for (int off = 16; off; off >>= 1)
            v += __shfl_xor_sync(FULL, v, off);

        __shared__ float s2[WARPS_PER_BLOCK];
        if (lane == 0) s2[tid >> 5] = v;
        __syncthreads();
        if (tid < 32) {
            float z = (tid < WARPS_PER_BLOCK) ? s2[tid] : 0.f;
#pragma unroll
            for (int off = 4; off; off >>= 1)
                z += __shfl_xor_sync(FULL, z, off);
            if (tid == 0) {
                out[0]  = z * (1.0f / (float)B_N);
                g_count = 0u;                       // reset for next graph replay
            }
        }
    }
}

extern "C" void kernel_launch(void* const* d_in, const int* in_sizes, int n_in,
                              void* d_out, int out_size)
{
    const int*   contexts = (const int*)  d_in[0];
    const int*   focus    = (const int*)  d_in[1];
    const float* wmask    = (const float*)d_in[2];
    const float* labels   = (const float*)d_in[3];
    const float* ctx_emb  = (const float*)d_in[4];
    const float* neg_emb  = (const float*)d_in[5];
    float*       out      = (float*)d_out;

    cbow_loss_kernel<<<NBLOCKS, THREADS>>>(contexts, focus, wmask, labels,
                                           ctx_emb, neg_emb, out);
}